// round 7
// baseline (speedup 1.0000x reference)
#include <cuda_runtime.h>

#define NN 50000
#define NE 800000
#define D_IN 256
#define D_HID 128
#define D_OUT 64

#define SCAN_B 1024
#define SCAN_NBLK ((NN + SCAN_B - 1) / SCAN_B)   // 49

// ---------------- static device scratch (no allocations; accessed ONLY from device code) ----------------
__device__ float g_bufA[(size_t)NN * D_HID];   // 25.6 MB
__device__ float g_bufB[(size_t)NN * D_HID];   // 25.6 MB
__device__ float g_dinv[NN];
__device__ int   g_deg[NN];
__device__ int   g_rowptr[NN + 1];
__device__ int   g_fill[NN];
__device__ int   g_blocksums[SCAN_NBLK];
__device__ int   g_csr_src[NE];
__device__ float g_csr_w[NE];
__device__ int   g_is64;   // 1 if edge_index is int64, 0 if int32 (derived from input each call)

// ---------------- edge index accessors ----------------
__device__ __forceinline__ int edge_src(const int* ei, int e) {
    if (g_is64) return ei[2 * e];            // low word of int64 (ids < 2^31)
    return ei[e];
}
__device__ __forceinline__ int edge_dst(const int* ei, int e) {
    if (g_is64) return ei[2 * NE + 2 * e];   // low word of int64 at offset NE elements
    return ei[NE + e];
}

// ---------------- dtype detection: int64 edges have all-odd-words == 0 ----------------
__global__ void k_detect(const int* __restrict__ ei) {
    if (threadIdx.x == 0 && blockIdx.x == 0) {
        int allzero = 1;
        for (int i = 0; i < 64; i++) {
            // sample odd 32-bit words spread across the first half of the buffer
            int idx = 2 * (i * (NE / 64) + 1) + 1;
            if (ei[idx] != 0) { allzero = 0; break; }
        }
        g_is64 = allzero;
    }
}

// ---------------- prep kernels ----------------
__global__ void k_zero_deg() {
    int i = blockIdx.x * blockDim.x + threadIdx.x;
    if (i < NN) g_deg[i] = 0;
}

__global__ void k_degcount(const int* __restrict__ ei) {
    int e = blockIdx.x * blockDim.x + threadIdx.x;
    if (e >= NE) return;
    int d = edge_dst(ei, e);
    if ((unsigned)d < NN) atomicAdd(&g_deg[d], 1);
}

__global__ void k_dinv() {
    int i = blockIdx.x * blockDim.x + threadIdx.x;
    if (i < NN) g_dinv[i] = rsqrtf((float)(g_deg[i] + 1));  // +1 self loop
}

// ---------------- exclusive scan of deg -> rowptr (3 stages) ----------------
__global__ void __launch_bounds__(SCAN_B) k_scan1() {
    __shared__ int sh[SCAN_B];
    int i = blockIdx.x * SCAN_B + threadIdx.x;
    int v = (i < NN) ? g_deg[i] : 0;
    sh[threadIdx.x] = v;
    __syncthreads();
    for (int off = 1; off < SCAN_B; off <<= 1) {
        int t = (threadIdx.x >= (unsigned)off) ? sh[threadIdx.x - off] : 0;
        __syncthreads();
        sh[threadIdx.x] += t;
        __syncthreads();
    }
    if (i < NN) g_rowptr[i] = sh[threadIdx.x] - v;   // block-local exclusive
    if (threadIdx.x == SCAN_B - 1) g_blocksums[blockIdx.x] = sh[SCAN_B - 1];
}

__global__ void k_scan2() {
    if (threadIdx.x == 0 && blockIdx.x == 0) {
        int acc = 0;
        for (int b = 0; b < SCAN_NBLK; b++) {
            int v = g_blocksums[b];
            g_blocksums[b] = acc;
            acc += v;
        }
    }
}

__global__ void k_scan3() {
    int i = blockIdx.x * blockDim.x + threadIdx.x;
    if (i < NN) {
        g_rowptr[i] += g_blocksums[i / SCAN_B];
        g_fill[i] = 0;
    }
    if (i == 0) g_rowptr[NN] = NE;
}

// ---------------- CSR fill (by dst), weight = dinv[s]*dinv[d] ----------------
__global__ void k_fill(const int* __restrict__ ei) {
    int e = blockIdx.x * blockDim.x + threadIdx.x;
    if (e >= NE) return;
    int s = edge_src(ei, e);
    int d = edge_dst(ei, e);
    if ((unsigned)s >= NN || (unsigned)d >= NN) return;  // defensive: never trap
    int pos = g_rowptr[d] + atomicAdd(&g_fill[d], 1);
    g_csr_src[pos] = s;
    g_csr_w[pos] = g_dinv[s] * g_dinv[d];
}

// ---------------- GEMM: H[M,BN] = X[M,K] @ W[K,BN] ----------------
// xsel: -1 -> use Xext, 0 -> g_bufA, 1 -> g_bufB.  osel: 0 -> g_bufA, 1 -> g_bufB.
template <int BN>
__global__ void __launch_bounds__(256) k_gemm(const float* __restrict__ Xext, int xsel, int osel,
                                              const float* __restrict__ W, int M, int K) {
    constexpr int BM = 64;
    constexpr int BK = 32;
    constexpr int CPT = BN / 16;

    const float* X = (xsel < 0) ? Xext : (xsel == 0 ? g_bufA : g_bufB);
    float* H = (osel == 0) ? g_bufA : g_bufB;

    __shared__ float Xs[BK][BM + 4];
    __shared__ float Ws[BK][BN];

    const int t = threadIdx.x;
    const int trow = t >> 4;
    const int tcol = t & 15;
    const int m0 = blockIdx.x * BM;

    float acc[4][CPT];
#pragma unroll
    for (int i = 0; i < 4; i++)
#pragma unroll
        for (int j = 0; j < CPT; j++) acc[i][j] = 0.0f;

    for (int kb = 0; kb < K; kb += BK) {
#pragma unroll
        for (int i = 0; i < 2; i++) {
            int idx = t + i * 256;
            int r = idx >> 3;
            int kq = idx & 7;
            float4 v = make_float4(0.f, 0.f, 0.f, 0.f);
            int gr = m0 + r;
            if (gr < M) v = *(const float4*)&X[(size_t)gr * K + kb + kq * 4];
            Xs[kq * 4 + 0][r] = v.x;
            Xs[kq * 4 + 1][r] = v.y;
            Xs[kq * 4 + 2][r] = v.z;
            Xs[kq * 4 + 3][r] = v.w;
        }
#pragma unroll
        for (int i = 0; i < (BK * BN / 4) / 256; i++) {
            int idx = t + i * 256;
            int k = idx / (BN / 4);
            int nq = idx % (BN / 4);
            *(float4*)&Ws[k][nq * 4] =
                *(const float4*)&W[(size_t)(kb + k) * BN + nq * 4];
        }
        __syncthreads();

#pragma unroll
        for (int k = 0; k < BK; k++) {
            float4 a4 = *(const float4*)&Xs[k][trow * 4];
            float av[4] = {a4.x, a4.y, a4.z, a4.w};
            float bv[CPT];
#pragma unroll
            for (int j = 0; j < CPT; j += 4) {
                float4 w4 = *(const float4*)&Ws[k][tcol * CPT + j];
                bv[j] = w4.x; bv[j + 1] = w4.y; bv[j + 2] = w4.z; bv[j + 3] = w4.w;
            }
#pragma unroll
            for (int i = 0; i < 4; i++)
#pragma unroll
                for (int j = 0; j < CPT; j++) acc[i][j] += av[i] * bv[j];
        }
        __syncthreads();
    }

#pragma unroll
    for (int i = 0; i < 4; i++) {
        int gr = m0 + trow * 4 + i;
        if (gr < M) {
#pragma unroll
            for (int j = 0; j < CPT; j += 4) {
                float4 o = make_float4(acc[i][j], acc[i][j + 1], acc[i][j + 2], acc[i][j + 3]);
                *(float4*)&H[(size_t)gr * BN + tcol * CPT + j] = o;
            }
        }
    }
}

// ---------------- fused gather: agg = sum_nbr(h[s]*w) + h[n]*dinv^2, +bias, relu ----------------
// One warp per node. hsel: 0 -> g_bufA, 1 -> g_bufB. osel: -1 -> Oext, 0 -> g_bufA, 1 -> g_bufB.
template <int F>
__global__ void __launch_bounds__(256) k_gather(int hsel, int osel, float* __restrict__ Oext,
                                                const float* __restrict__ bias) {
    const float* h = (hsel == 0) ? g_bufA : g_bufB;
    float* out = (osel < 0) ? Oext : (osel == 0 ? g_bufA : g_bufB);

    int warp = (blockIdx.x * blockDim.x + threadIdx.x) >> 5;
    int lane = threadIdx.x & 31;
    if (warp >= NN) return;

    int beg = g_rowptr[warp];
    int end = g_rowptr[warp + 1];

    if (F == 128) {
        float4 acc = make_float4(0.f, 0.f, 0.f, 0.f);
        for (int e = beg; e < end; e++) {
            int s = g_csr_src[e];
            float w = g_csr_w[e];
            float4 v = *(const float4*)&h[(size_t)s * F + lane * 4];
            acc.x += v.x * w; acc.y += v.y * w; acc.z += v.z * w; acc.w += v.w * w;
        }
        float di = g_dinv[warp];
        float s2 = di * di;
        float4 vs = *(const float4*)&h[(size_t)warp * F + lane * 4];
        acc.x += vs.x * s2; acc.y += vs.y * s2; acc.z += vs.z * s2; acc.w += vs.w * s2;
        float4 bv = *(const float4*)&bias[lane * 4];
        acc.x = fmaxf(acc.x + bv.x, 0.f);
        acc.y = fmaxf(acc.y + bv.y, 0.f);
        acc.z = fmaxf(acc.z + bv.z, 0.f);
        acc.w = fmaxf(acc.w + bv.w, 0.f);
        *(float4*)&out[(size_t)warp * F + lane * 4] = acc;
    } else {  // F == 64
        float2 acc = make_float2(0.f, 0.f);
        for (int e = beg; e < end; e++) {
            int s = g_csr_src[e];
            float w = g_csr_w[e];
            float2 v = *(const float2*)&h[(size_t)s * F + lane * 2];
            acc.x += v.x * w; acc.y += v.y * w;
        }
        float di = g_dinv[warp];
        float s2 = di * di;
        float2 vs = *(const float2*)&h[(size_t)warp * F + lane * 2];
        acc.x += vs.x * s2; acc.y += vs.y * s2;
        float2 bv = *(const float2*)&bias[lane * 2];
        acc.x = fmaxf(acc.x + bv.x, 0.f);
        acc.y = fmaxf(acc.y + bv.y, 0.f);
        *(float2*)&out[(size_t)warp * F + lane * 2] = acc;
    }
}

// ---------------- launch ----------------
extern "C" void kernel_launch(void* const* d_in, const int* in_sizes, int n_in,
                              void* d_out, int out_size) {
    const float* x  = (const float*)d_in[0];
    const int*   ei = (const int*)d_in[1];   // raw words; dtype detected on device
    const float* W1 = (const float*)d_in[2];
    const float* b1 = (const float*)d_in[3];
    const float* W2 = (const float*)d_in[4];
    const float* b2 = (const float*)d_in[5];
    const float* W3 = (const float*)d_in[6];
    const float* b3 = (const float*)d_in[7];
    float* out = (float*)d_out;

    const int T = 256;

    // ---- graph prep: dtype detect, degree, norm, CSR by dst ----
    k_detect<<<1, 32>>>(ei);
    k_zero_deg<<<(NN + T - 1) / T, T>>>();
    k_degcount<<<(NE + T - 1) / T, T>>>(ei);
    k_dinv<<<(NN + T - 1) / T, T>>>();
    k_scan1<<<SCAN_NBLK, SCAN_B>>>();
    k_scan2<<<1, 32>>>();
    k_scan3<<<(NN + T - 1) / T, T>>>();
    k_fill<<<(NE + T - 1) / T, T>>>(ei);

    const int GM = (NN + 63) / 64;
    const int GW = (NN * 32 + T - 1) / T;   // warp-per-node grid

    // ----- layer 1: x[50000,256] @ W1 -> bufA; gather bufA -> bufB -----
    k_gemm<128><<<GM, T>>>(x, -1, 0, W1, NN, D_IN);
    k_gather<128><<<GW, T>>>(0, 1, nullptr, b1);

    // ----- layer 2: bufB @ W2 -> bufA; gather bufA -> bufB -----
    k_gemm<128><<<GM, T>>>(nullptr, 1, 0, W2, NN, D_HID);
    k_gather<128><<<GW, T>>>(0, 1, nullptr, b2);

    // ----- layer 3: bufB @ W3 -> bufA; gather bufA -> out -----
    k_gemm<64><<<GM, T>>>(nullptr, 1, 0, W3, NN, D_HID);
    k_gather<64><<<GW, T>>>(0, -1, out, b3);
}

// round 8
// speedup vs baseline: 1.3734x; 1.3734x over previous
#include <cuda_runtime.h>
#include <mma.h>
using namespace nvcuda;

#define NN 50000
#define NNP 50048          // padded to multiple of 128 for full-tile tensor stores
#define NE 800000
#define D_IN 256
#define D_HID 128
#define D_OUT 64

#define SCAN_B 1024
#define SCAN_NBLK ((NN + SCAN_B - 1) / SCAN_B)   // 49

// ---------------- static device scratch (no allocations; accessed ONLY from device code) ----------------
__device__ float g_bufA[(size_t)NNP * D_HID];   // 25.6 MB (row-padded)
__device__ float g_bufB[(size_t)NNP * D_HID];   // 25.6 MB
__device__ float g_dinv[NN];
__device__ int   g_deg[NN];
__device__ int   g_rowptr[NN + 1];
__device__ int   g_fill[NN];
__device__ int   g_blocksums[SCAN_NBLK];
__device__ int   g_csr_src[NE];
__device__ float g_csr_w[NE];
__device__ int   g_is64;   // 1 if edge_index is int64, 0 if int32 (derived from input each call)

// ---------------- edge index accessors ----------------
__device__ __forceinline__ int edge_src(const int* ei, int e) {
    if (g_is64) return ei[2 * e];
    return ei[e];
}
__device__ __forceinline__ int edge_dst(const int* ei, int e) {
    if (g_is64) return ei[2 * NE + 2 * e];
    return ei[NE + e];
}

// ---------------- dtype detection: int64 edges have all-odd-words == 0 ----------------
__global__ void k_detect(const int* __restrict__ ei) {
    if (threadIdx.x == 0 && blockIdx.x == 0) {
        int allzero = 1;
        for (int i = 0; i < 64; i++) {
            int idx = 2 * (i * (NE / 64) + 1) + 1;
            if (ei[idx] != 0) { allzero = 0; break; }
        }
        g_is64 = allzero;
    }
}

// ---------------- prep kernels ----------------
__global__ void k_zero_deg() {
    int i = blockIdx.x * blockDim.x + threadIdx.x;
    if (i < NN) g_deg[i] = 0;
}

__global__ void k_degcount(const int* __restrict__ ei) {
    int e = blockIdx.x * blockDim.x + threadIdx.x;
    if (e >= NE) return;
    int d = edge_dst(ei, e);
    if ((unsigned)d < NN) atomicAdd(&g_deg[d], 1);
}

__global__ void k_dinv() {
    int i = blockIdx.x * blockDim.x + threadIdx.x;
    if (i < NN) g_dinv[i] = rsqrtf((float)(g_deg[i] + 1));  // +1 self loop
}

// ---------------- exclusive scan of deg -> rowptr (3 stages) ----------------
__global__ void __launch_bounds__(SCAN_B) k_scan1() {
    __shared__ int sh[SCAN_B];
    int i = blockIdx.x * SCAN_B + threadIdx.x;
    int v = (i < NN) ? g_deg[i] : 0;
    sh[threadIdx.x] = v;
    __syncthreads();
    for (int off = 1; off < SCAN_B; off <<= 1) {
        int t = (threadIdx.x >= (unsigned)off) ? sh[threadIdx.x - off] : 0;
        __syncthreads();
        sh[threadIdx.x] += t;
        __syncthreads();
    }
    if (i < NN) g_rowptr[i] = sh[threadIdx.x] - v;
    if (threadIdx.x == SCAN_B - 1) g_blocksums[blockIdx.x] = sh[SCAN_B - 1];
}

__global__ void k_scan2() {
    if (threadIdx.x == 0 && blockIdx.x == 0) {
        int acc = 0;
        for (int b = 0; b < SCAN_NBLK; b++) {
            int v = g_blocksums[b];
            g_blocksums[b] = acc;
            acc += v;
        }
    }
}

__global__ void k_scan3() {
    int i = blockIdx.x * blockDim.x + threadIdx.x;
    if (i < NN) {
        g_rowptr[i] += g_blocksums[i / SCAN_B];
        g_fill[i] = 0;
    }
    if (i == 0) g_rowptr[NN] = NE;
}

// ---------------- CSR fill (by dst), weight = dinv[s]*dinv[d] ----------------
__global__ void k_fill(const int* __restrict__ ei) {
    int e = blockIdx.x * blockDim.x + threadIdx.x;
    if (e >= NE) return;
    int s = edge_src(ei, e);
    int d = edge_dst(ei, e);
    if ((unsigned)s >= NN || (unsigned)d >= NN) return;
    int pos = g_rowptr[d] + atomicAdd(&g_fill[d], 1);
    g_csr_src[pos] = s;
    g_csr_w[pos] = g_dinv[s] * g_dinv[d];
}

// ---------------- tensor-core GEMM (tf32 wmma): H[M,BN] = X[M,K] @ W[K,BN] ----------------
// Block tile 128 x BN, 256 threads (8 warps), warp tile 32 x (BN/2).
// xsel: -1 -> Xext, 0 -> g_bufA, 1 -> g_bufB.  osel: 0 -> g_bufA, 1 -> g_bufB.
template <int BN>
__global__ void __launch_bounds__(256) k_gemm_tc(const float* __restrict__ Xext, int xsel, int osel,
                                                 const float* __restrict__ W, int M, int K) {
    constexpr int BM = 128;
    constexpr int BK = 32;
    constexpr int XPAD = 4;                 // row stride 36 floats (144B, 16B-mult)
    constexpr int WPAD = 8;                 // row stride BN+8 floats (16B-mult)
    constexpr int CF = BN / 32;             // b-frags per warp (128->4, 64->2)

    const float* X = (xsel < 0) ? Xext : (xsel == 0 ? g_bufA : g_bufB);
    float* H = (osel == 0) ? g_bufA : g_bufB;

    __shared__ float Xs[BM][BK + XPAD];
    __shared__ float Ws[BK][BN + WPAD];

    const int t = threadIdx.x;
    const int warp = t >> 5;
    const int wr = warp & 3;            // warp row 0..3  -> rows wr*32
    const int wc = warp >> 2;           // warp col 0..1  -> cols wc*(BN/2)
    const int m0 = blockIdx.x * BM;

    wmma::fragment<wmma::accumulator, 16, 16, 8, float> c[2][CF];
#pragma unroll
    for (int i = 0; i < 2; i++)
#pragma unroll
        for (int j = 0; j < CF; j++) wmma::fill_fragment(c[i][j], 0.0f);

    for (int kb = 0; kb < K; kb += BK) {
        // stage X tile [BM][BK]
#pragma unroll
        for (int it = 0; it < (BM * BK / 4) / 256; it++) {
            int idx = t + it * 256;              // 0..1023
            int r = idx >> 3;                    // 0..127
            int kq = idx & 7;                    // float4 group in BK
            float4 v = make_float4(0.f, 0.f, 0.f, 0.f);
            int gr = m0 + r;
            if (gr < M) v = *(const float4*)&X[(size_t)gr * K + kb + kq * 4];
            *(float4*)&Xs[r][kq * 4] = v;
        }
        // stage W tile [BK][BN]
#pragma unroll
        for (int it = 0; it < (BK * BN / 4) / 256; it++) {
            int idx = t + it * 256;
            int r = idx / (BN / 4);
            int c4 = idx % (BN / 4);
            *(float4*)&Ws[r][c4 * 4] = *(const float4*)&W[(size_t)(kb + r) * BN + c4 * 4];
        }
        __syncthreads();

#pragma unroll
        for (int ks = 0; ks < BK / 8; ks++) {
            wmma::fragment<wmma::matrix_a, 16, 16, 8, wmma::precision::tf32, wmma::row_major> a[2];
            wmma::fragment<wmma::matrix_b, 16, 16, 8, wmma::precision::tf32, wmma::row_major> b[CF];
#pragma unroll
            for (int i = 0; i < 2; i++) {
                wmma::load_matrix_sync(a[i], &Xs[wr * 32 + i * 16][ks * 8], BK + XPAD);
#pragma unroll
                for (int e = 0; e < a[i].num_elements; e++)
                    a[i].x[e] = wmma::__float_to_tf32(a[i].x[e]);
            }
#pragma unroll
            for (int j = 0; j < CF; j++) {
                wmma::load_matrix_sync(b[j], &Ws[ks * 8][wc * (BN / 2) + j * 16], BN + WPAD);
#pragma unroll
                for (int e = 0; e < b[j].num_elements; e++)
                    b[j].x[e] = wmma::__float_to_tf32(b[j].x[e]);
            }
#pragma unroll
            for (int i = 0; i < 2; i++)
#pragma unroll
                for (int j = 0; j < CF; j++)
                    wmma::mma_sync(c[i][j], a[i], b[j], c[i][j]);
        }
        __syncthreads();
    }

    // epilogue: full-tile stores into row-padded H (rows >= M land in pad region)
#pragma unroll
    for (int i = 0; i < 2; i++) {
        int gr0 = m0 + wr * 32 + i * 16;
#pragma unroll
        for (int j = 0; j < CF; j++) {
            int gc0 = wc * (BN / 2) + j * 16;
            wmma::store_matrix_sync(&H[(size_t)gr0 * BN + gc0], c[i][j], BN, wmma::mem_row_major);
        }
    }
}

// ---------------- fused gather: agg = sum_nbr(h[s]*w) + h[n]*dinv^2, +bias, relu ----------------
// One warp per node. hsel: 0 -> g_bufA, 1 -> g_bufB. osel: -1 -> Oext, 0 -> g_bufA, 1 -> g_bufB.
template <int F>
__global__ void __launch_bounds__(256) k_gather(int hsel, int osel, float* __restrict__ Oext,
                                                const float* __restrict__ bias) {
    const float* h = (hsel == 0) ? g_bufA : g_bufB;
    float* out = (osel < 0) ? Oext : (osel == 0 ? g_bufA : g_bufB);

    int warp = (blockIdx.x * blockDim.x + threadIdx.x) >> 5;
    int lane = threadIdx.x & 31;
    if (warp >= NN) return;

    int beg = g_rowptr[warp];
    int end = g_rowptr[warp + 1];

    if (F == 128) {
        float4 acc = make_float4(0.f, 0.f, 0.f, 0.f);
        for (int e = beg; e < end; e++) {
            int s = g_csr_src[e];
            float w = g_csr_w[e];
            float4 v = *(const float4*)&h[(size_t)s * F + lane * 4];
            acc.x += v.x * w; acc.y += v.y * w; acc.z += v.z * w; acc.w += v.w * w;
        }
        float di = g_dinv[warp];
        float s2 = di * di;
        float4 vs = *(const float4*)&h[(size_t)warp * F + lane * 4];
        acc.x += vs.x * s2; acc.y += vs.y * s2; acc.z += vs.z * s2; acc.w += vs.w * s2;
        float4 bv = *(const float4*)&bias[lane * 4];
        acc.x = fmaxf(acc.x + bv.x, 0.f);
        acc.y = fmaxf(acc.y + bv.y, 0.f);
        acc.z = fmaxf(acc.z + bv.z, 0.f);
        acc.w = fmaxf(acc.w + bv.w, 0.f);
        *(float4*)&out[(size_t)warp * F + lane * 4] = acc;
    } else {  // F == 64
        float2 acc = make_float2(0.f, 0.f);
        for (int e = beg; e < end; e++) {
            int s = g_csr_src[e];
            float w = g_csr_w[e];
            float2 v = *(const float2*)&h[(size_t)s * F + lane * 2];
            acc.x += v.x * w; acc.y += v.y * w;
        }
        float di = g_dinv[warp];
        float s2 = di * di;
        float2 vs = *(const float2*)&h[(size_t)warp * F + lane * 2];
        acc.x += vs.x * s2; acc.y += vs.y * s2;
        float2 bv = *(const float2*)&bias[lane * 2];
        acc.x = fmaxf(acc.x + bv.x, 0.f);
        acc.y = fmaxf(acc.y + bv.y, 0.f);
        *(float2*)&out[(size_t)warp * F + lane * 2] = acc;
    }
}

// ---------------- launch ----------------
extern "C" void kernel_launch(void* const* d_in, const int* in_sizes, int n_in,
                              void* d_out, int out_size) {
    const float* x  = (const float*)d_in[0];
    const int*   ei = (const int*)d_in[1];   // raw words; dtype detected on device
    const float* W1 = (const float*)d_in[2];
    const float* b1 = (const float*)d_in[3];
    const float* W2 = (const float*)d_in[4];
    const float* b2 = (const float*)d_in[5];
    const float* W3 = (const float*)d_in[6];
    const float* b3 = (const float*)d_in[7];
    float* out = (float*)d_out;

    const int T = 256;

    // ---- graph prep: dtype detect, degree, norm, CSR by dst ----
    k_detect<<<1, 32>>>(ei);
    k_zero_deg<<<(NN + T - 1) / T, T>>>();
    k_degcount<<<(NE + T - 1) / T, T>>>(ei);
    k_dinv<<<(NN + T - 1) / T, T>>>();
    k_scan1<<<SCAN_NBLK, SCAN_B>>>();
    k_scan2<<<1, 32>>>();
    k_scan3<<<(NN + T - 1) / T, T>>>();
    k_fill<<<(NE + T - 1) / T, T>>>(ei);

    const int GT = (NN + 127) / 128;        // tensor GEMM grid (covers padded rows)
    const int GW = (NN * 32 + T - 1) / T;   // warp-per-node grid

    // ----- layer 1: x[50000,256] @ W1 -> bufA; gather bufA -> bufB -----
    k_gemm_tc<128><<<GT, T>>>(x, -1, 0, W1, NN, D_IN);
    k_gather<128><<<GW, T>>>(0, 1, nullptr, b1);

    // ----- layer 2: bufB @ W2 -> bufA; gather bufA -> bufB -----
    k_gemm_tc<128><<<GT, T>>>(nullptr, 1, 0, W2, NN, D_HID);
    k_gather<128><<<GW, T>>>(0, 1, nullptr, b2);

    // ----- layer 3: bufB @ W3 -> bufA; gather bufA -> out -----
    k_gemm_tc<64><<<GT, T>>>(nullptr, 1, 0, W3, NN, D_HID);
    k_gather<64><<<GW, T>>>(0, -1, out, b3);
}

// round 10
// speedup vs baseline: 1.4891x; 1.0842x over previous
#include <cuda_runtime.h>
#include <mma.h>
using namespace nvcuda;

#define NN 50000
#define NNP 50048          // padded to multiple of 128 for full-tile tensor stores
#define NE 800000
#define D_IN 256
#define D_HID 128
#define D_OUT 64

#define SCAN_B 1024
#define SCAN_NBLK ((NN + SCAN_B - 1) / SCAN_B)   // 49

// ---------------- static device scratch ----------------
__device__ float g_bufA[(size_t)NNP * D_HID];
__device__ float g_bufB[(size_t)NNP * D_HID];
__device__ float g_dinv[NN];
__device__ int   g_deg[NN];
__device__ int   g_rowptr[NN + 1];
__device__ int   g_fill[NN];
__device__ int   g_blocksums[SCAN_NBLK];
__device__ int   g_csr_src[NE];
__device__ float g_csr_w[NE];
__device__ int   g_is64;

// ---------------- edge index accessors ----------------
__device__ __forceinline__ int edge_src(const int* ei, int e) {
    if (g_is64) return ei[2 * e];
    return ei[e];
}
__device__ __forceinline__ int edge_dst(const int* ei, int e) {
    if (g_is64) return ei[2 * NE + 2 * e];
    return ei[NE + e];
}

__global__ void k_detect(const int* __restrict__ ei) {
    if (threadIdx.x == 0 && blockIdx.x == 0) {
        int allzero = 1;
        for (int i = 0; i < 64; i++) {
            int idx = 2 * (i * (NE / 64) + 1) + 1;
            if (ei[idx] != 0) { allzero = 0; break; }
        }
        g_is64 = allzero;
    }
}

// ---------------- prep ----------------
__global__ void k_zero_deg() {
    int i = blockIdx.x * blockDim.x + threadIdx.x;
    if (i < NN) g_deg[i] = 0;
}

__global__ void k_degcount(const int* __restrict__ ei) {
    int e = blockIdx.x * blockDim.x + threadIdx.x;
    if (e >= NE) return;
    int d = edge_dst(ei, e);
    if ((unsigned)d < NN) atomicAdd(&g_deg[d], 1);
}

__global__ void __launch_bounds__(SCAN_B) k_scan1() {
    __shared__ int sh[SCAN_B];
    int i = blockIdx.x * SCAN_B + threadIdx.x;
    int v = (i < NN) ? g_deg[i] : 0;
    sh[threadIdx.x] = v;
    __syncthreads();
    for (int off = 1; off < SCAN_B; off <<= 1) {
        int t = (threadIdx.x >= (unsigned)off) ? sh[threadIdx.x - off] : 0;
        __syncthreads();
        sh[threadIdx.x] += t;
        __syncthreads();
    }
    if (i < NN) g_rowptr[i] = sh[threadIdx.x] - v;
    if (threadIdx.x == SCAN_B - 1) g_blocksums[blockIdx.x] = sh[SCAN_B - 1];
}

__global__ void k_scan2() {
    if (threadIdx.x == 0 && blockIdx.x == 0) {
        int acc = 0;
        for (int b = 0; b < SCAN_NBLK; b++) {
            int v = g_blocksums[b];
            g_blocksums[b] = acc;
            acc += v;
        }
    }
}

// scan finalize + dinv fused
__global__ void k_scan3() {
    int i = blockIdx.x * blockDim.x + threadIdx.x;
    if (i < NN) {
        g_rowptr[i] += g_blocksums[i / SCAN_B];
        g_fill[i] = 0;
        g_dinv[i] = rsqrtf((float)(g_deg[i] + 1));  // +1 self loop
    }
    if (i == 0) g_rowptr[NN] = NE;
}

__global__ void k_fill(const int* __restrict__ ei) {
    int e = blockIdx.x * blockDim.x + threadIdx.x;
    if (e >= NE) return;
    int s = edge_src(ei, e);
    int d = edge_dst(ei, e);
    if ((unsigned)s >= NN || (unsigned)d >= NN) return;
    int pos = g_rowptr[d] + atomicAdd(&g_fill[d], 1);
    g_csr_src[pos] = s;
    g_csr_w[pos] = g_dinv[s] * g_dinv[d];
}

// ---------------- tensor-core GEMM (tf32 wmma), tf32 conversion at staging ----------------
template <int BN>
__global__ void __launch_bounds__(256) k_gemm_tc(const float* __restrict__ Xext, int xsel, int osel,
                                                 const float* __restrict__ W, int M, int K) {
    constexpr int BM = 128;
    constexpr int BK = 32;
    constexpr int XPAD = 4;
    constexpr int WPAD = 8;
    constexpr int CF = BN / 32;

    const float* X = (xsel < 0) ? Xext : (xsel == 0 ? g_bufA : g_bufB);
    float* H = (osel == 0) ? g_bufA : g_bufB;

    __shared__ float Xs[BM][BK + XPAD];
    __shared__ float Ws[BK][BN + WPAD];

    const int t = threadIdx.x;
    const int warp = t >> 5;
    const int wr = warp & 3;
    const int wc = warp >> 2;
    const int m0 = blockIdx.x * BM;

    wmma::fragment<wmma::accumulator, 16, 16, 8, float> c[2][CF];
#pragma unroll
    for (int i = 0; i < 2; i++)
#pragma unroll
        for (int j = 0; j < CF; j++) wmma::fill_fragment(c[i][j], 0.0f);

    for (int kb = 0; kb < K; kb += BK) {
#pragma unroll
        for (int it = 0; it < (BM * BK / 4) / 256; it++) {
            int idx = t + it * 256;
            int r = idx >> 3;
            int kq = idx & 7;
            float4 v = make_float4(0.f, 0.f, 0.f, 0.f);
            int gr = m0 + r;
            if (gr < M) v = *(const float4*)&X[(size_t)gr * K + kb + kq * 4];
            v.x = wmma::__float_to_tf32(v.x);
            v.y = wmma::__float_to_tf32(v.y);
            v.z = wmma::__float_to_tf32(v.z);
            v.w = wmma::__float_to_tf32(v.w);
            *(float4*)&Xs[r][kq * 4] = v;
        }
#pragma unroll
        for (int it = 0; it < (BK * BN / 4) / 256; it++) {
            int idx = t + it * 256;
            int r = idx / (BN / 4);
            int c4 = idx % (BN / 4);
            float4 v = *(const float4*)&W[(size_t)(kb + r) * BN + c4 * 4];
            v.x = wmma::__float_to_tf32(v.x);
            v.y = wmma::__float_to_tf32(v.y);
            v.z = wmma::__float_to_tf32(v.z);
            v.w = wmma::__float_to_tf32(v.w);
            *(float4*)&Ws[r][c4 * 4] = v;
        }
        __syncthreads();

#pragma unroll
        for (int ks = 0; ks < BK / 8; ks++) {
            wmma::fragment<wmma::matrix_a, 16, 16, 8, wmma::precision::tf32, wmma::row_major> a[2];
            wmma::fragment<wmma::matrix_b, 16, 16, 8, wmma::precision::tf32, wmma::row_major> b[CF];
#pragma unroll
            for (int i = 0; i < 2; i++)
                wmma::load_matrix_sync(a[i], &Xs[wr * 32 + i * 16][ks * 8], BK + XPAD);
#pragma unroll
            for (int j = 0; j < CF; j++)
                wmma::load_matrix_sync(b[j], &Ws[ks * 8][wc * (BN / 2) + j * 16], BN + WPAD);
#pragma unroll
            for (int i = 0; i < 2; i++)
#pragma unroll
                for (int j = 0; j < CF; j++)
                    wmma::mma_sync(c[i][j], a[i], b[j], c[i][j]);
        }
        __syncthreads();
    }

#pragma unroll
    for (int i = 0; i < 2; i++) {
        int gr0 = m0 + wr * 32 + i * 16;
#pragma unroll
        for (int j = 0; j < CF; j++) {
            int gc0 = wc * (BN / 2) + j * 16;
            wmma::store_matrix_sync(&H[(size_t)gr0 * BN + gc0], c[i][j], BN, wmma::mem_row_major);
        }
    }
}

// ---------------- fused gather F=128: warp/node, edge loop unrolled x2 ----------------
__global__ void __launch_bounds__(256) k_gather128(int hsel, int osel,
                                                   const float* __restrict__ bias) {
    const float* __restrict__ h = (hsel == 0) ? g_bufA : g_bufB;
    float* __restrict__ out = (osel == 0) ? g_bufA : g_bufB;

    int warp = (blockIdx.x * blockDim.x + threadIdx.x) >> 5;
    int lane = threadIdx.x & 31;
    if (warp >= NN) return;

    int beg = g_rowptr[warp];
    int end = g_rowptr[warp + 1];

    float4 acc0 = make_float4(0.f, 0.f, 0.f, 0.f);
    float4 acc1 = make_float4(0.f, 0.f, 0.f, 0.f);
    int e = beg;
    for (; e + 1 < end; e += 2) {
        int s0 = g_csr_src[e];
        int s1 = g_csr_src[e + 1];
        float w0 = g_csr_w[e];
        float w1 = g_csr_w[e + 1];
        float4 v0 = *(const float4*)&h[(size_t)s0 * 128 + lane * 4];
        float4 v1 = *(const float4*)&h[(size_t)s1 * 128 + lane * 4];
        acc0.x += v0.x * w0; acc0.y += v0.y * w0; acc0.z += v0.z * w0; acc0.w += v0.w * w0;
        acc1.x += v1.x * w1; acc1.y += v1.y * w1; acc1.z += v1.z * w1; acc1.w += v1.w * w1;
    }
    if (e < end) {
        int s0 = g_csr_src[e];
        float w0 = g_csr_w[e];
        float4 v0 = *(const float4*)&h[(size_t)s0 * 128 + lane * 4];
        acc0.x += v0.x * w0; acc0.y += v0.y * w0; acc0.z += v0.z * w0; acc0.w += v0.w * w0;
    }
    float di = g_dinv[warp];
    float s2 = di * di;
    float4 vs = *(const float4*)&h[(size_t)warp * 128 + lane * 4];
    acc0.x += acc1.x + vs.x * s2;
    acc0.y += acc1.y + vs.y * s2;
    acc0.z += acc1.z + vs.z * s2;
    acc0.w += acc1.w + vs.w * s2;
    float4 bv = *(const float4*)&bias[lane * 4];
    acc0.x = fmaxf(acc0.x + bv.x, 0.f);
    acc0.y = fmaxf(acc0.y + bv.y, 0.f);
    acc0.z = fmaxf(acc0.z + bv.z, 0.f);
    acc0.w = fmaxf(acc0.w + bv.w, 0.f);
    *(float4*)&out[(size_t)warp * 128 + lane * 4] = acc0;
}

// ---------------- fused gather F=64: warp/node, half-warp per edge stream ----------------
__global__ void __launch_bounds__(256) k_gather64(int hsel, float* __restrict__ out,
                                                  const float* __restrict__ bias) {
    const float* __restrict__ h = (hsel == 0) ? g_bufA : g_bufB;

    int warp = (blockIdx.x * blockDim.x + threadIdx.x) >> 5;
    int lane = threadIdx.x & 31;
    int half = lane >> 4;       // 0 or 1
    int l16 = lane & 15;        // column group: floats [l16*4 .. l16*4+3]
    if (warp >= NN) return;

    int beg = g_rowptr[warp];
    int end = g_rowptr[warp + 1];

    float4 acc = make_float4(0.f, 0.f, 0.f, 0.f);
    for (int e = beg + half; e < end; e += 2) {
        int s = g_csr_src[e];
        float w = g_csr_w[e];
        float4 v = *(const float4*)&h[(size_t)s * 64 + l16 * 4];
        acc.x += v.x * w; acc.y += v.y * w; acc.z += v.z * w; acc.w += v.w * w;
    }
    // combine the two half-warp partials (columns match across halves)
    acc.x += __shfl_xor_sync(0xffffffffu, acc.x, 16);
    acc.y += __shfl_xor_sync(0xffffffffu, acc.y, 16);
    acc.z += __shfl_xor_sync(0xffffffffu, acc.z, 16);
    acc.w += __shfl_xor_sync(0xffffffffu, acc.w, 16);

    if (half == 0) {
        float di = g_dinv[warp];
        float s2 = di * di;
        float4 vs = *(const float4*)&h[(size_t)warp * 64 + l16 * 4];
        acc.x += vs.x * s2; acc.y += vs.y * s2; acc.z += vs.z * s2; acc.w += vs.w * s2;
        float4 bv = *(const float4*)&bias[l16 * 4];
        acc.x = fmaxf(acc.x + bv.x, 0.f);
        acc.y = fmaxf(acc.y + bv.y, 0.f);
        acc.z = fmaxf(acc.z + bv.z, 0.f);
        acc.w = fmaxf(acc.w + bv.w, 0.f);
        *(float4*)&out[(size_t)warp * 64 + l16 * 4] = acc;
    }
}

// ---------------- launch ----------------
extern "C" void kernel_launch(void* const* d_in, const int* in_sizes, int n_in,
                              void* d_out, int out_size) {
    const float* x  = (const float*)d_in[0];
    const int*   ei = (const int*)d_in[1];
    const float* W1 = (const float*)d_in[2];
    const float* b1 = (const float*)d_in[3];
    const float* W2 = (const float*)d_in[4];
    const float* b2 = (const float*)d_in[5];
    const float* W3 = (const float*)d_in[6];
    const float* b3 = (const float*)d_in[7];
    float* out = (float*)d_out;

    const int T = 256;

    // ---- graph prep ----
    k_detect<<<1, 32>>>(ei);
    k_zero_deg<<<(NN + T - 1) / T, T>>>();
    k_degcount<<<(NE + T - 1) / T, T>>>(ei);
    k_scan1<<<SCAN_NBLK, SCAN_B>>>();
    k_scan2<<<1, 32>>>();
    k_scan3<<<(NN + T - 1) / T, T>>>();   // rowptr finalize + fill reset + dinv
    k_fill<<<(NE + T - 1) / T, T>>>(ei);

    const int GT = (NN + 127) / 128;
    const int GW = (NN * 32 + T - 1) / T;

    // ----- layer 1 -----
    k_gemm_tc<128><<<GT, T>>>(x, -1, 0, W1, NN, D_IN);
    k_gather128<<<GW, T>>>(0, 1, b1);

    // ----- layer 2 -----
    k_gemm_tc<128><<<GT, T>>>(nullptr, 1, 0, W2, NN, D_HID);
    k_gather128<<<GW, T>>>(0, 1, b2);

    // ----- layer 3 -----
    k_gemm_tc<64><<<GT, T>>>(nullptr, 1, 0, W3, NN, D_HID);
    k_gather64<<<GW, T>>>(0, out, b3);
}